// round 16
// baseline (speedup 1.0000x reference)
#include <cuda_runtime.h>

// CapsuleLayer dynamic routing, factored + Gram form, v11.
// X[B=128, I=1152, J=128], W[J=128, K=32, D=32], out V[B=128, K=32, D=32]
//  kG  : G[k] = W_k W_k^T + it0 colsum partials
//  kY  : per (k, 16 batches): G fully staged; y -> z = G y -> T (mode1 += -> Tsum)
//  k2  : per (split of 128 i, b): single-buffer x chunks (58KB smem -> 3-4 CTAs/SM,
//        grid 1152 for balance), two 128-thread groups; GEMM2 -> exp -> norm -> GEMM1
//  kOut: s = y*W -> squash -> out

#define BB 128
#define II 1152
#define JJ 128
#define KK 32
#define DD 32
#define KD 1024
#define NSPLIT 9
#define ILEN 128
#define CI 64
#define NCH 2
#define C2P 36
#define NYP (NSPLIT*2)   // 18 y-partial slots
#define YMP 20

typedef unsigned long long u64;

#define FMA2(d,a,b,c) asm("fma.rn.f32x2 %0, %1, %2, %3;" : "=l"(d) : "l"(a), "l"(b), "l"(c))
#define ADD2(d,a,b)   asm("add.rn.f32x2 %0, %1, %2;" : "=l"(d) : "l"(a), "l"(b))
#define PACK2(d,s)    asm("mov.b64 %0, {%1, %1};" : "=l"(d) : "r"(__float_as_uint(s)))
#define GBAR(id)      asm volatile("bar.sync %0, 128;" :: "r"(id) : "memory")
#define CP_COMMIT()   asm volatile("cp.async.commit_group;\n" ::: "memory")
#define CP_WAIT0()    asm volatile("cp.async.wait_group 0;\n" ::: "memory")
#define CP16(dst,src) asm volatile("cp.async.cg.shared.global [%0], [%1], 16;\n" :: "r"(dst), "l"(src))

__device__ float g_T[(size_t)BB * KK * JJ];             // [b][k][j]
__device__ float g_yp[(size_t)BB * NYP * KK * JJ];      // [b][slot][k][j]
__device__ float g_ycol[(size_t)BB * 4 * JJ];           // [b][p][j]
__device__ float g_G[(size_t)KK * JJ * JJ];             // [k][j'][j]

// ===================== kG: Gram build + it0 colsum =====================
__global__ __launch_bounds__(256)
void kG(const float* __restrict__ W, const float* __restrict__ X)
{
    const int t = threadIdx.x;
    if (blockIdx.x < 32) {
        __shared__ float wsm[JJ * 33];
        const int k = blockIdx.x;
        #pragma unroll
        for (int ee = 0; ee < 16; ++ee) {
            const int idx = t + ee * 256;            // j*32 + d
            wsm[(idx >> 5) * 33 + (idx & 31)] = W[(size_t)(idx >> 5) * KD + k * DD + (idx & 31)];
        }
        __syncthreads();
        const int j = t & 127, half = t >> 7;
        float rj[32];
        #pragma unroll
        for (int d = 0; d < 32; ++d) rj[d] = wsm[j * 33 + d];
        float* Gk = g_G + (size_t)k * (JJ * JJ);
        #pragma unroll 2
        for (int jp = 0; jp < 64; ++jp) {
            const int jpg = half * 64 + jp;
            float acc = 0.f;
            #pragma unroll
            for (int d = 0; d < 32; ++d)
                acc = fmaf(rj[d], wsm[jpg * 33 + d], acc);
            Gk[jpg * JJ + j] = acc;
        }
        return;
    }
    __shared__ ulonglong2 sred[256];
    const int bid = blockIdx.x - 32;
    const int b = bid & 127, p = bid >> 7;
    const int j4 = t & 31, ih = t >> 5;
    const float* xp = X + (size_t)b * (II * JJ) + (size_t)(p * 288 + ih * 36) * JJ + j4 * 4;
    u64 s0 = 0, s1 = 0;
    #pragma unroll 4
    for (int ii = 0; ii < 36; ++ii) {
        ulonglong2 v = *(const ulonglong2*)(xp + (size_t)ii * JJ);
        ADD2(s0, s0, v.x); ADD2(s1, s1, v.y);
    }
    sred[ih * 32 + j4] = make_ulonglong2(s0, s1);
    __syncthreads();
    if (t < 32) {
        u64 a0 = 0, a1 = 0;
        #pragma unroll
        for (int h = 0; h < 8; ++h) {
            ulonglong2 v = sred[h * 32 + t];
            ADD2(a0, a0, v.x); ADD2(a1, a1, v.y);
        }
        ((ulonglong2*)(g_ycol + (size_t)(b * 4 + p) * JJ))[t] = make_ulonglong2(a0, a1);
    }
}

// ===================== kY: y -> z = G y -> scale -> T (accumulating) =====================
#define KY_G   0                    // 16384 f (all of G[k])
#define KY_YT  16384                // 128*20 = 2560 f
#define KY_SB  (KY_YT + 2560)       // 64
#define KY_SC  (KY_SB + 64)         // 16
#define KY_FLOATS (KY_SC + 16)
#define KY_SMEM (KY_FLOATS * 4)

__global__ __launch_bounds__(256, 3)
void kY(int mode)                   // 0: y from colsum, T = scl*z ; 1: y from g_yp, T += scl*z
{
    extern __shared__ float sm[];
    float* Gs  = sm + KY_G;
    float* ymt = sm + KY_YT;
    float* ssb = sm + KY_SB;
    float* scl = sm + KY_SC;

    const int k = blockIdx.x, b0 = blockIdx.y * 16;
    const int t = threadIdx.x;
    const float* Gk = g_G + (size_t)k * (JJ * JJ);
    const unsigned gsa = (unsigned)__cvta_generic_to_shared(Gs);

    // stage ALL of G[k] (64KB), one shot
    #pragma unroll
    for (int e = 0; e < 16; ++e) {
        const int idx = t + e * 256;
        CP16(gsa + (unsigned)idx * 16u, (const float4*)Gk + idx);
    }
    CP_COMMIT();

    // stage y transposed: ymt[j][b]  (overlaps the G copy)
    {
        const int bL = t >> 6, jj = (t & 63) * 2;
        #pragma unroll
        for (int pass = 0; pass < 4; ++pass) {
            const int b = pass * 4 + bL;
            float v0, v1;
            if (mode == 0) {
                const float* yc = g_ycol + (size_t)(b0 + b) * 4 * JJ;
                v0 = (yc[jj]   + yc[128 + jj] + yc[256 + jj] + yc[384 + jj]) * (1.0f / 32.0f);
                v1 = (yc[jj+1] + yc[129 + jj] + yc[257 + jj] + yc[385 + jj]) * (1.0f / 32.0f);
            } else {
                const float* yp = g_yp + (size_t)(b0 + b) * NYP * KK * JJ + (size_t)k * JJ + jj;
                v0 = 0.f; v1 = 0.f;
                #pragma unroll
                for (int s = 0; s < NYP; ++s) {
                    const float2 u = *(const float2*)(yp + (size_t)s * KK * JJ);
                    v0 += u.x; v1 += u.y;
                }
            }
            ymt[jj * YMP + b] = v0;
            ymt[(jj + 1) * YMP + b] = v1;
        }
    }
    CP_WAIT0();
    __syncthreads();                 // G + ymt visible

    // z[b][j], 8 b per thread; pure LDS + FMA over all 128 jp
    const int j = t & 127, bh = t >> 7;
    float z[8];
    #pragma unroll
    for (int r = 0; r < 8; ++r) z[r] = 0.f;
    #pragma unroll 4
    for (int jp = 0; jp < JJ; ++jp) {
        const float g = Gs[jp * JJ + j];                        // conflict-free
        const float4 y0 = *(const float4*)(ymt + jp * YMP + bh * 8);       // bcast
        const float4 y1 = *(const float4*)(ymt + jp * YMP + bh * 8 + 4);
        z[0] = fmaf(y0.x, g, z[0]); z[1] = fmaf(y0.y, g, z[1]);
        z[2] = fmaf(y0.z, g, z[2]); z[3] = fmaf(y0.w, g, z[3]);
        z[4] = fmaf(y1.x, g, z[4]); z[5] = fmaf(y1.y, g, z[5]);
        z[6] = fmaf(y1.z, g, z[6]); z[7] = fmaf(y1.w, g, z[7]);
    }

    // ss[b] = sum_j y z
    {
        float ssp[8];
        #pragma unroll
        for (int r = 0; r < 8; ++r)
            ssp[r] = ymt[j * YMP + bh * 8 + r] * z[r];
        #pragma unroll
        for (int off = 16; off > 0; off >>= 1) {
            #pragma unroll
            for (int r = 0; r < 8; ++r)
                ssp[r] += __shfl_xor_sync(0xffffffffu, ssp[r], off);
        }
        const int w = t >> 5;
        if ((t & 31) == 0) {
            #pragma unroll
            for (int r = 0; r < 8; ++r)
                ssb[(w & 3) * 16 + bh * 8 + r] = ssp[r];
        }
    }
    __syncthreads();
    if (t < 16) {
        const float ss = ssb[t] + ssb[16 + t] + ssb[32 + t] + ssb[48 + t];
        scl[t] = ss / (1.0f + ss) * rsqrtf(ss + 1e-7f);
    }
    __syncthreads();

    #pragma unroll
    for (int r = 0; r < 8; ++r) {
        const int b = bh * 8 + r;
        const size_t ti = (size_t)(b0 + b) * KK * JJ + (size_t)k * JJ + j;
        float tv = z[r] * scl[b];
        if (mode) tv += g_T[ti];         // Tsum = T0 + T1
        g_T[ti] = tv;
    }
}

// ===================== kOut: s = y*W -> squash -> out =====================
#define KO_W  0                     // 128*33 = 4224
#define KO_Y  4224                  // 32*128 = 4096
#define KO_FLOATS (KO_Y + 4096)
#define KO_SMEM (KO_FLOATS * 4)

__global__ __launch_bounds__(256)
void kOut(const float* __restrict__ W, float* __restrict__ out)
{
    extern __shared__ float sm[];
    float* wsm = sm + KO_W;
    float* ymb = sm + KO_Y;

    const int k = blockIdx.x, b0 = blockIdx.y * 32;
    const int t = threadIdx.x;

    #pragma unroll
    for (int ee = 0; ee < 16; ++ee) {
        const int idx = t + ee * 256;
        wsm[(idx >> 5) * 33 + (idx & 31)] = W[(size_t)(idx >> 5) * KD + k * DD + (idx & 31)];
    }
    {
        const int bL = t >> 6, jj = (t & 63) * 2;
        #pragma unroll
        for (int pass = 0; pass < 8; ++pass) {
            const int b = pass * 4 + bL;
            const float* yp = g_yp + (size_t)(b0 + b) * NYP * KK * JJ + (size_t)k * JJ + jj;
            float v0 = 0.f, v1 = 0.f;
            #pragma unroll
            for (int s = 0; s < NYP; ++s) {
                const float2 u = *(const float2*)(yp + (size_t)s * KK * JJ);
                v0 += u.x; v1 += u.y;
            }
            ymb[b * JJ + jj] = v0;
            ymb[b * JJ + jj + 1] = v1;
        }
    }
    __syncthreads();

    const int b = t >> 3, d0 = t & 7;
    float s4[4] = {0.f, 0.f, 0.f, 0.f};
    #pragma unroll 4
    for (int j = 0; j < JJ; ++j) {
        const float yv = ymb[b * JJ + j];
        #pragma unroll
        for (int q = 0; q < 4; ++q)
            s4[q] = fmaf(yv, wsm[j * 33 + d0 + 8 * q], s4[q]);
    }
    float ssp = s4[0]*s4[0] + s4[1]*s4[1] + s4[2]*s4[2] + s4[3]*s4[3];
    ssp += __shfl_xor_sync(0xffffffffu, ssp, 1, 8);
    ssp += __shfl_xor_sync(0xffffffffu, ssp, 2, 8);
    ssp += __shfl_xor_sync(0xffffffffu, ssp, 4, 8);
    const float scale = ssp / (1.0f + ssp) * rsqrtf(ssp + 1e-7f);
    #pragma unroll
    for (int q = 0; q < 4; ++q)
        out[(size_t)(b0 + b) * KK * DD + k * DD + d0 + 8 * q] = s4[q] * scale;
}

// ===================== k2: single-buffer streaming GEMM2 -> softmax -> GEMM1 =====================
#define K2_XS  0         // 8192 f (XOR swizzle)
#define K2_TM  8192      // 4096 f
#define K2_C2  12288     // 64*36: c at [0,32), partial sums at [32,36)
#define K2_FLOATS 14592  // 58368 B -> 3-4 CTAs/SM
#define K2_SMEM (K2_FLOATS * 4)

__global__ __launch_bounds__(256, 3)
void k2_stream(const float* __restrict__ X)
{
    extern __shared__ float sm[];
    float* xs = sm + K2_XS;
    float* Tm = sm + K2_TM;
    float* c2 = sm + K2_C2;

    const int b = blockIdx.y, split = blockIdx.x;
    const int t = threadIdx.x, lane = t & 31, w = t >> 5;
    const int kg = w & 3, ih = w >> 2;
    const int gt = t & 127;
    const int barid = 1 + ih;
    const int iL = ih * 32 + lane;

    const float* __restrict__ xg = X + (size_t)b * (II * JJ);
    const unsigned xsa = (unsigned)__cvta_generic_to_shared(xs);

    {
        const float4* Tg = (const float4*)(g_T + (size_t)b * KK * JJ);
        #pragma unroll
        for (int ee = 0; ee < 4; ++ee)
            ((float4*)Tm)[t + ee * 256] = Tg[t + ee * 256];
    }
    u64 a1[8][2];
    #pragma unroll
    for (int q = 0; q < 8; ++q) { a1[q][0] = 0; a1[q][1] = 0; }
    __syncthreads();                            // Tm visible; groups aligned

    for (int ch = 0; ch < NCH; ++ch) {
        const int ibase = split * ILEN + ch * CI;

        // stage own group's 32 rows (cp.async, XOR-swizzled)
        #pragma unroll
        for (int ee = 0; ee < 8; ++ee) {
            const int e4 = gt + ee * 128;       // il_loc*32 + j4
            const int il = ih * 32 + (e4 >> 5), j4 = e4 & 31;
            const unsigned dst = xsa + (unsigned)(il * 128 + ((j4 ^ (il & 31)) << 2)) * 4u;
            CP16(dst, xg + (size_t)(ibase + il) * JJ + j4 * 4);
        }
        CP_COMMIT();
        CP_WAIT0();
        GBAR(barid);                            // group's rows visible

        // GEMM2: warp = 8 k x 32 i (lane) x 128 j  (logits = X * Tsum)
        u64 a2[8];
        #pragma unroll
        for (int q = 0; q < 8; ++q) a2[q] = 0;
        {
            const float* xr = xs + iL * 128;
            #pragma unroll 4
            for (int jq = 0; jq < 32; ++jq) {
                const ulonglong2 xv = *(const ulonglong2*)(xr + ((jq ^ lane) << 2));
                #pragma unroll
                for (int q = 0; q < 8; ++q) {
                    const ulonglong2 tq = *(const ulonglong2*)(Tm + (kg * 8 + q) * JJ + jq * 4);
                    FMA2(a2[q], tq.x, xv.x, a2[q]);
                    FMA2(a2[q], tq.y, xv.y, a2[q]);
                }
            }
        }
        float ex[8], ssloc = 0.f;
        #pragma unroll
        for (int q = 0; q < 8; ++q) {
            const float2 f = *(float2*)&a2[q];
            ex[q] = __expf(f.x + f.y);          // |logit| small: max-sub not needed
            ssloc += ex[q];
        }
        c2[iL * C2P + 32 + kg] = ssloc;
        GBAR(barid);

        {
            const float4 sp = *(const float4*)(c2 + iL * C2P + 32);
            const float inv = 1.0f / (sp.x + sp.y + sp.z + sp.w);
            *(float4*)(c2 + iL * C2P + kg * 8) =
                make_float4(ex[0] * inv, ex[1] * inv, ex[2] * inv, ex[3] * inv);
            *(float4*)(c2 + iL * C2P + kg * 8 + 4) =
                make_float4(ex[4] * inv, ex[5] * inv, ex[6] * inv, ex[7] * inv);
        }
        GBAR(barid);

        // GEMM1: warp = 8 k x 32 i (own half) x 128 j
        #pragma unroll 2
        for (int ii = 0; ii < 32; ++ii) {
            const int i = ih * 32 + ii;
            const ulonglong2 xv = *(const ulonglong2*)(xs + i * 128 + ((lane ^ ii) << 2));
            const float4 c0 = *(const float4*)(c2 + i * C2P + kg * 8);
            const float4 c1 = *(const float4*)(c2 + i * C2P + kg * 8 + 4);
            u64 cc;
            PACK2(cc, c0.x); FMA2(a1[0][0], cc, xv.x, a1[0][0]); FMA2(a1[0][1], cc, xv.y, a1[0][1]);
            PACK2(cc, c0.y); FMA2(a1[1][0], cc, xv.x, a1[1][0]); FMA2(a1[1][1], cc, xv.y, a1[1][1]);
            PACK2(cc, c0.z); FMA2(a1[2][0], cc, xv.x, a1[2][0]); FMA2(a1[2][1], cc, xv.y, a1[2][1]);
            PACK2(cc, c0.w); FMA2(a1[3][0], cc, xv.x, a1[3][0]); FMA2(a1[3][1], cc, xv.y, a1[3][1]);
            PACK2(cc, c1.x); FMA2(a1[4][0], cc, xv.x, a1[4][0]); FMA2(a1[4][1], cc, xv.y, a1[4][1]);
            PACK2(cc, c1.y); FMA2(a1[5][0], cc, xv.x, a1[5][0]); FMA2(a1[5][1], cc, xv.y, a1[5][1]);
            PACK2(cc, c1.z); FMA2(a1[6][0], cc, xv.x, a1[6][0]); FMA2(a1[6][1], cc, xv.y, a1[6][1]);
            PACK2(cc, c1.w); FMA2(a1[7][0], cc, xv.x, a1[7][0]); FMA2(a1[7][1], cc, xv.y, a1[7][1]);
        }
        GBAR(barid);                            // xs/c2 free for next chunk
    }

    float* yp = g_yp + ((size_t)(b * NSPLIT + split) * 2 + ih) * KK * JJ;
    #pragma unroll
    for (int q = 0; q < 8; ++q)
        *(ulonglong2*)(yp + (kg * 8 + q) * JJ + lane * 4) =
            make_ulonglong2(a1[q][0], a1[q][1]);
}

extern "C" void kernel_launch(void* const* d_in, const int* in_sizes, int n_in,
                              void* d_out, int out_size)
{
    (void)in_sizes; (void)n_in; (void)out_size;
    const float* X = (const float*)d_in[0];   // [128, 1152, 128] f32
    const float* W = (const float*)d_in[1];   // [128, 32, 32] f32
    float* out = (float*)d_out;               // [128, 32, 32] f32

    cudaFuncSetAttribute(kY, cudaFuncAttributeMaxDynamicSharedMemorySize, KY_SMEM);
    cudaFuncSetAttribute(kOut, cudaFuncAttributeMaxDynamicSharedMemorySize, KO_SMEM);
    cudaFuncSetAttribute(k2_stream, cudaFuncAttributeMaxDynamicSharedMemorySize, K2_SMEM);

    kG<<<32 + 512, 256>>>(W, X);
    kY<<<dim3(KK, 8), 256, KY_SMEM>>>(0);                    // T = T0
    k2_stream<<<dim3(NSPLIT, BB), 256, K2_SMEM>>>(X);        // c1 from X*T0
    kY<<<dim3(KK, 8), 256, KY_SMEM>>>(1);                    // T = T0 + T1
    k2_stream<<<dim3(NSPLIT, BB), 256, K2_SMEM>>>(X);        // c2 from X*(T0+T1)
    kOut<<<dim3(KK, 4), 256, KO_SMEM>>>(W, out);
}

// round 17
// speedup vs baseline: 1.0860x; 1.0860x over previous
#include <cuda_runtime.h>

// CapsuleLayer dynamic routing, factored + Gram form, v12 (= v10 + unroll tuning).
// X[B=128, I=1152, J=128], W[J=128, K=32, D=32], out V[B=128, K=32, D=32]
//  kG  : G[k] = W_k W_k^T + it0 colsum partials
//  kY  : per (k, 16 batches): G fully staged once via cp.async,
//        y -> z = G y -> T (mode1 accumulates: Tsum = T0+T1, bl = X*Tsum)
//  k2  : per (split, b): cp.async dbuf x chunks, two 128-thread groups;
//        GEMM2 -> exp -> norm -> GEMM1
//  kOut: s = y*W -> squash -> out

#define BB 128
#define II 1152
#define JJ 128
#define KK 32
#define DD 32
#define KD 1024
#define NSPLIT 2
#define ILEN 576
#define CI 64
#define NCH 9
#define C2P 36
#define NYP (NSPLIT*2)
#define YMP 20

typedef unsigned long long u64;

#define FMA2(d,a,b,c) asm("fma.rn.f32x2 %0, %1, %2, %3;" : "=l"(d) : "l"(a), "l"(b), "l"(c))
#define ADD2(d,a,b)   asm("add.rn.f32x2 %0, %1, %2;" : "=l"(d) : "l"(a), "l"(b))
#define PACK2(d,s)    asm("mov.b64 %0, {%1, %1};" : "=l"(d) : "r"(__float_as_uint(s)))
#define GBAR(id)      asm volatile("bar.sync %0, 128;" :: "r"(id) : "memory")
#define CP_COMMIT()   asm volatile("cp.async.commit_group;\n" ::: "memory")
#define CP_WAIT0()    asm volatile("cp.async.wait_group 0;\n" ::: "memory")
#define CP16(dst,src) asm volatile("cp.async.cg.shared.global [%0], [%1], 16;\n" :: "r"(dst), "l"(src))

__device__ float g_T[(size_t)BB * KK * JJ];             // [b][k][j]
__device__ float g_yp[(size_t)BB * NYP * KK * JJ];      // [b][slot][k][j]
__device__ float g_ycol[(size_t)BB * 4 * JJ];           // [b][p][j]
__device__ float g_G[(size_t)KK * JJ * JJ];             // [k][j'][j]

// ===================== kG: Gram build + it0 colsum =====================
__global__ __launch_bounds__(256)
void kG(const float* __restrict__ W, const float* __restrict__ X)
{
    const int t = threadIdx.x;
    if (blockIdx.x < 32) {
        __shared__ float wsm[JJ * 33];
        const int k = blockIdx.x;
        #pragma unroll
        for (int ee = 0; ee < 16; ++ee) {
            const int idx = t + ee * 256;            // j*32 + d
            wsm[(idx >> 5) * 33 + (idx & 31)] = W[(size_t)(idx >> 5) * KD + k * DD + (idx & 31)];
        }
        __syncthreads();
        const int j = t & 127, half = t >> 7;
        float rj[32];
        #pragma unroll
        for (int d = 0; d < 32; ++d) rj[d] = wsm[j * 33 + d];
        float* Gk = g_G + (size_t)k * (JJ * JJ);
        #pragma unroll 2
        for (int jp = 0; jp < 64; ++jp) {
            const int jpg = half * 64 + jp;
            float acc = 0.f;
            #pragma unroll
            for (int d = 0; d < 32; ++d)
                acc = fmaf(rj[d], wsm[jpg * 33 + d], acc);
            Gk[jpg * JJ + j] = acc;
        }
        return;
    }
    __shared__ ulonglong2 sred[256];
    const int bid = blockIdx.x - 32;
    const int b = bid & 127, p = bid >> 7;
    const int j4 = t & 31, ih = t >> 5;
    const float* xp = X + (size_t)b * (II * JJ) + (size_t)(p * 288 + ih * 36) * JJ + j4 * 4;
    u64 s0 = 0, s1 = 0;
    #pragma unroll 8
    for (int ii = 0; ii < 36; ++ii) {
        ulonglong2 v = *(const ulonglong2*)(xp + (size_t)ii * JJ);
        ADD2(s0, s0, v.x); ADD2(s1, s1, v.y);
    }
    sred[ih * 32 + j4] = make_ulonglong2(s0, s1);
    __syncthreads();
    if (t < 32) {
        u64 a0 = 0, a1 = 0;
        #pragma unroll
        for (int h = 0; h < 8; ++h) {
            ulonglong2 v = sred[h * 32 + t];
            ADD2(a0, a0, v.x); ADD2(a1, a1, v.y);
        }
        ((ulonglong2*)(g_ycol + (size_t)(b * 4 + p) * JJ))[t] = make_ulonglong2(a0, a1);
    }
}

// ===================== kY: y -> z = G y -> scale -> T (accumulating) =====================
#define KY_G   0                    // 16384 f (all of G[k])
#define KY_YT  16384                // 128*20 = 2560 f
#define KY_SB  (KY_YT + 2560)       // 64
#define KY_SC  (KY_SB + 64)         // 16
#define KY_FLOATS (KY_SC + 16)
#define KY_SMEM (KY_FLOATS * 4)

__global__ __launch_bounds__(256, 3)
void kY(int mode)                   // 0: y from colsum, T = scl*z ; 1: y from g_yp, T += scl*z
{
    extern __shared__ float sm[];
    float* Gs  = sm + KY_G;
    float* ymt = sm + KY_YT;
    float* ssb = sm + KY_SB;
    float* scl = sm + KY_SC;

    const int k = blockIdx.x, b0 = blockIdx.y * 16;
    const int t = threadIdx.x;
    const float* Gk = g_G + (size_t)k * (JJ * JJ);
    const unsigned gsa = (unsigned)__cvta_generic_to_shared(Gs);

    // stage ALL of G[k] (64KB), one shot
    #pragma unroll
    for (int e = 0; e < 16; ++e) {
        const int idx = t + e * 256;
        CP16(gsa + (unsigned)idx * 16u, (const float4*)Gk + idx);
    }
    CP_COMMIT();

    // stage y transposed: ymt[j][b]  (overlaps the G copy)
    {
        const int bL = t >> 6, jj = (t & 63) * 2;
        #pragma unroll
        for (int pass = 0; pass < 4; ++pass) {
            const int b = pass * 4 + bL;
            float v0, v1;
            if (mode == 0) {
                const float* yc = g_ycol + (size_t)(b0 + b) * 4 * JJ;
                v0 = (yc[jj]   + yc[128 + jj] + yc[256 + jj] + yc[384 + jj]) * (1.0f / 32.0f);
                v1 = (yc[jj+1] + yc[129 + jj] + yc[257 + jj] + yc[385 + jj]) * (1.0f / 32.0f);
            } else {
                const float* yp = g_yp + (size_t)(b0 + b) * NYP * KK * JJ + (size_t)k * JJ + jj;
                v0 = 0.f; v1 = 0.f;
                #pragma unroll
                for (int s = 0; s < NYP; ++s) {
                    const float2 u = *(const float2*)(yp + (size_t)s * KK * JJ);
                    v0 += u.x; v1 += u.y;
                }
            }
            ymt[jj * YMP + b] = v0;
            ymt[(jj + 1) * YMP + b] = v1;
        }
    }
    CP_WAIT0();
    __syncthreads();                 // G + ymt visible

    // z[b][j], 8 b per thread; pure LDS + FMA over all 128 jp
    const int j = t & 127, bh = t >> 7;
    float z[8];
    #pragma unroll
    for (int r = 0; r < 8; ++r) z[r] = 0.f;
    #pragma unroll 8
    for (int jp = 0; jp < JJ; ++jp) {
        const float g = Gs[jp * JJ + j];                        // conflict-free
        const float4 y0 = *(const float4*)(ymt + jp * YMP + bh * 8);       // bcast
        const float4 y1 = *(const float4*)(ymt + jp * YMP + bh * 8 + 4);
        z[0] = fmaf(y0.x, g, z[0]); z[1] = fmaf(y0.y, g, z[1]);
        z[2] = fmaf(y0.z, g, z[2]); z[3] = fmaf(y0.w, g, z[3]);
        z[4] = fmaf(y1.x, g, z[4]); z[5] = fmaf(y1.y, g, z[5]);
        z[6] = fmaf(y1.z, g, z[6]); z[7] = fmaf(y1.w, g, z[7]);
    }

    // ss[b] = sum_j y z
    {
        float ssp[8];
        #pragma unroll
        for (int r = 0; r < 8; ++r)
            ssp[r] = ymt[j * YMP + bh * 8 + r] * z[r];
        #pragma unroll
        for (int off = 16; off > 0; off >>= 1) {
            #pragma unroll
            for (int r = 0; r < 8; ++r)
                ssp[r] += __shfl_xor_sync(0xffffffffu, ssp[r], off);
        }
        const int w = t >> 5;
        if ((t & 31) == 0) {
            #pragma unroll
            for (int r = 0; r < 8; ++r)
                ssb[(w & 3) * 16 + bh * 8 + r] = ssp[r];
        }
    }
    __syncthreads();
    if (t < 16) {
        const float ss = ssb[t] + ssb[16 + t] + ssb[32 + t] + ssb[48 + t];
        scl[t] = ss / (1.0f + ss) * rsqrtf(ss + 1e-7f);
    }
    __syncthreads();

    #pragma unroll
    for (int r = 0; r < 8; ++r) {
        const int b = bh * 8 + r;
        const size_t ti = (size_t)(b0 + b) * KK * JJ + (size_t)k * JJ + j;
        float tv = z[r] * scl[b];
        if (mode) tv += g_T[ti];         // Tsum = T0 + T1
        g_T[ti] = tv;
    }
}

// ===================== kOut: s = y*W -> squash -> out =====================
#define KO_W  0                     // 128*33 = 4224
#define KO_Y  4224                  // 32*128 = 4096
#define KO_FLOATS (KO_Y + 4096)
#define KO_SMEM (KO_FLOATS * 4)

__global__ __launch_bounds__(256)
void kOut(const float* __restrict__ W, float* __restrict__ out)
{
    extern __shared__ float sm[];
    float* wsm = sm + KO_W;
    float* ymb = sm + KO_Y;

    const int k = blockIdx.x, b0 = blockIdx.y * 32;
    const int t = threadIdx.x;

    #pragma unroll
    for (int ee = 0; ee < 16; ++ee) {
        const int idx = t + ee * 256;
        wsm[(idx >> 5) * 33 + (idx & 31)] = W[(size_t)(idx >> 5) * KD + k * DD + (idx & 31)];
    }
    {
        const int bL = t >> 6, jj = (t & 63) * 2;
        #pragma unroll
        for (int pass = 0; pass < 8; ++pass) {
            const int b = pass * 4 + bL;
            const float* yp = g_yp + (size_t)(b0 + b) * NYP * KK * JJ + (size_t)k * JJ + jj;
            float v0 = 0.f, v1 = 0.f;
            #pragma unroll
            for (int s = 0; s < NYP; ++s) {
                const float2 u = *(const float2*)(yp + (size_t)s * KK * JJ);
                v0 += u.x; v1 += u.y;
            }
            ymb[b * JJ + jj] = v0;
            ymb[b * JJ + jj + 1] = v1;
        }
    }
    __syncthreads();

    const int b = t >> 3, d0 = t & 7;
    float s4[4] = {0.f, 0.f, 0.f, 0.f};
    #pragma unroll 4
    for (int j = 0; j < JJ; ++j) {
        const float yv = ymb[b * JJ + j];
        #pragma unroll
        for (int q = 0; q < 4; ++q)
            s4[q] = fmaf(yv, wsm[j * 33 + d0 + 8 * q], s4[q]);
    }
    float ssp = s4[0]*s4[0] + s4[1]*s4[1] + s4[2]*s4[2] + s4[3]*s4[3];
    ssp += __shfl_xor_sync(0xffffffffu, ssp, 1, 8);
    ssp += __shfl_xor_sync(0xffffffffu, ssp, 2, 8);
    ssp += __shfl_xor_sync(0xffffffffu, ssp, 4, 8);
    const float scale = ssp / (1.0f + ssp) * rsqrtf(ssp + 1e-7f);
    #pragma unroll
    for (int q = 0; q < 4; ++q)
        out[(size_t)(b0 + b) * KK * DD + k * DD + d0 + 8 * q] = s4[q] * scale;
}

// ===================== k2: cp.async pipelined GEMM2 -> softmax -> GEMM1 =====================
#define K2_XS0 0         // buf0: 8192 f (XOR swizzle)
#define K2_XS1 8192      // buf1: 8192 f
#define K2_TM  16384     // 4096 f
#define K2_C2  20480     // 64*36: c at [0,32), partial sums at [32,36)
#define K2_FLOATS 22784
#define K2_SMEM (K2_FLOATS * 4)

__global__ __launch_bounds__(256, 2)
void k2_stream(const float* __restrict__ X)
{
    extern __shared__ float sm[];
    float* Tm = sm + K2_TM;
    float* c2 = sm + K2_C2;

    const int b = blockIdx.y, split = blockIdx.x;
    const int t = threadIdx.x, lane = t & 31, w = t >> 5;
    const int kg = w & 3, ih = w >> 2;
    const int gt = t & 127;
    const int barid = 1 + ih;
    const int iL = ih * 32 + lane;

    const float* __restrict__ xg = X + (size_t)b * (II * JJ);
    const unsigned smbase = (unsigned)__cvta_generic_to_shared(sm);

    {
        const float4* Tg = (const float4*)(g_T + (size_t)b * KK * JJ);
        #pragma unroll
        for (int ee = 0; ee < 4; ++ee)
            ((float4*)Tm)[t + ee * 256] = Tg[t + ee * 256];
    }
    u64 a1[8][2];
    #pragma unroll
    for (int q = 0; q < 8; ++q) { a1[q][0] = 0; a1[q][1] = 0; }

    // preload chunk 0 into buf0 (own group's rows)
    {
        const int ibase = split * ILEN;
        #pragma unroll
        for (int ee = 0; ee < 8; ++ee) {
            const int e4 = gt + ee * 128;
            const int il = ih * 32 + (e4 >> 5), j4 = e4 & 31;
            const unsigned dst = smbase + (unsigned)(il * 128 + ((j4 ^ (il & 31)) << 2)) * 4u;
            CP16(dst, xg + (size_t)(ibase + il) * JJ + j4 * 4);
        }
        CP_COMMIT();
    }
    __syncthreads();                            // Tm visible; groups aligned

    for (int ch = 0; ch < NCH; ++ch) {
        const int ibase = split * ILEN + ch * CI;
        const float* xb = sm + ((ch & 1) ? K2_XS1 : K2_XS0);

        CP_WAIT0();
        GBAR(barid);   // chunk data in; prev chunk's GEMM1 done

        if (ch + 1 < NCH) {
            const unsigned boff = ((ch & 1) ? K2_XS0 : K2_XS1) * 4u;
            const float* src = xg + (size_t)(ibase + CI) * JJ;
            #pragma unroll
            for (int ee = 0; ee < 8; ++ee) {
                const int e4 = gt + ee * 128;
                const int il = ih * 32 + (e4 >> 5), j4 = e4 & 31;
                const unsigned dst = smbase + boff + (unsigned)(il * 128 + ((j4 ^ (il & 31)) << 2)) * 4u;
                CP16(dst, src + (size_t)il * JJ + j4 * 4);
            }
            CP_COMMIT();
        }

        // GEMM2: warp = 8 k x 32 i (lane) x 128 j  (logits = X * Tsum)
        u64 a2[8];
        #pragma unroll
        for (int q = 0; q < 8; ++q) a2[q] = 0;
        {
            const float* xr = xb + iL * 128;
            #pragma unroll 4
            for (int jq = 0; jq < 32; ++jq) {
                const ulonglong2 xv = *(const ulonglong2*)(xr + ((jq ^ lane) << 2));
                #pragma unroll
                for (int q = 0; q < 8; ++q) {
                    const ulonglong2 tq = *(const ulonglong2*)(Tm + (kg * 8 + q) * JJ + jq * 4);
                    FMA2(a2[q], tq.x, xv.x, a2[q]);
                    FMA2(a2[q], tq.y, xv.y, a2[q]);
                }
            }
        }
        float ex[8], ssloc = 0.f;
        #pragma unroll
        for (int q = 0; q < 8; ++q) {
            const float2 f = *(float2*)&a2[q];
            ex[q] = __expf(f.x + f.y);          // |logit| small: max-sub not needed
            ssloc += ex[q];
        }
        c2[iL * C2P + 32 + kg] = ssloc;
        GBAR(barid);

        {
            const float4 sp = *(const float4*)(c2 + iL * C2P + 32);
            const float inv = 1.0f / (sp.x + sp.y + sp.z + sp.w);
            *(float4*)(c2 + iL * C2P + kg * 8) =
                make_float4(ex[0] * inv, ex[1] * inv, ex[2] * inv, ex[3] * inv);
            *(float4*)(c2 + iL * C2P + kg * 8 + 4) =
                make_float4(ex[4] * inv, ex[5] * inv, ex[6] * inv, ex[7] * inv);
        }
        GBAR(barid);

        // GEMM1: warp = 8 k x 32 i (own half) x 128 j
        #pragma unroll 2
        for (int ii = 0; ii < 32; ++ii) {
            const int i = ih * 32 + ii;
            const ulonglong2 xv = *(const ulonglong2*)(xb + i * 128 + ((lane ^ ii) << 2));
            const float4 c0 = *(const float4*)(c2 + i * C2P + kg * 8);
            const float4 c1 = *(const float4*)(c2 + i * C2P + kg * 8 + 4);
            u64 cc;
            PACK2(cc, c0.x); FMA2(a1[0][0], cc, xv.x, a1[0][0]); FMA2(a1[0][1], cc, xv.y, a1[0][1]);
            PACK2(cc, c0.y); FMA2(a1[1][0], cc, xv.x, a1[1][0]); FMA2(a1[1][1], cc, xv.y, a1[1][1]);
            PACK2(cc, c0.z); FMA2(a1[2][0], cc, xv.x, a1[2][0]); FMA2(a1[2][1], cc, xv.y, a1[2][1]);
            PACK2(cc, c0.w); FMA2(a1[3][0], cc, xv.x, a1[3][0]); FMA2(a1[3][1], cc, xv.y, a1[3][1]);
            PACK2(cc, c1.x); FMA2(a1[4][0], cc, xv.x, a1[4][0]); FMA2(a1[4][1], cc, xv.y, a1[4][1]);
            PACK2(cc, c1.y); FMA2(a1[5][0], cc, xv.x, a1[5][0]); FMA2(a1[5][1], cc, xv.y, a1[5][1]);
            PACK2(cc, c1.z); FMA2(a1[6][0], cc, xv.x, a1[6][0]); FMA2(a1[6][1], cc, xv.y, a1[6][1]);
            PACK2(cc, c1.w); FMA2(a1[7][0], cc, xv.x, a1[7][0]); FMA2(a1[7][1], cc, xv.y, a1[7][1]);
        }
        // loop-top GBAR orders these reads vs. c2/buffer reuse
    }

    float* yp = g_yp + ((size_t)(b * NSPLIT + split) * 2 + ih) * KK * JJ;
    #pragma unroll
    for (int q = 0; q < 8; ++q)
        *(ulonglong2*)(yp + (kg * 8 + q) * JJ + lane * 4) =
            make_ulonglong2(a1[q][0], a1[q][1]);
}

extern "C" void kernel_launch(void* const* d_in, const int* in_sizes, int n_in,
                              void* d_out, int out_size)
{
    (void)in_sizes; (void)n_in; (void)out_size;
    const float* X = (const float*)d_in[0];   // [128, 1152, 128] f32
    const float* W = (const float*)d_in[1];   // [128, 32, 32] f32
    float* out = (float*)d_out;               // [128, 32, 32] f32

    cudaFuncSetAttribute(kY, cudaFuncAttributeMaxDynamicSharedMemorySize, KY_SMEM);
    cudaFuncSetAttribute(kOut, cudaFuncAttributeMaxDynamicSharedMemorySize, KO_SMEM);
    cudaFuncSetAttribute(k2_stream, cudaFuncAttributeMaxDynamicSharedMemorySize, K2_SMEM);

    kG<<<32 + 512, 256>>>(W, X);
    kY<<<dim3(KK, 8), 256, KY_SMEM>>>(0);                    // T = T0
    k2_stream<<<dim3(NSPLIT, BB), 256, K2_SMEM>>>(X);        // c1 from X*T0
    kY<<<dim3(KK, 8), 256, KY_SMEM>>>(1);                    // T = T0 + T1
    k2_stream<<<dim3(NSPLIT, BB), 256, K2_SMEM>>>(X);        // c2 from X*(T0+T1)
    kOut<<<dim3(KK, 4), 256, KO_SMEM>>>(W, out);
}